// round 1
// baseline (speedup 1.0000x reference)
#include <cuda_runtime.h>
#include <cuda_bf16.h>

#define N_NODES 100000
#define E_EDGES 1600000
#define IN_DIM  128
#define KH      8
#define DH      16
#define F       128          // KH*DH
#define NEG_SLOPE 0.2f

// ---------------- scratch (device globals; allocation-free) ----------------
__device__ float g_feat_src[N_NODES * F];   // 51.2 MB
__device__ float g_el[N_NODES * KH];
__device__ float g_er[N_NODES * KH];
__device__ float g_e[E_EDGES * KH];         // 51.2 MB (logits, then exp)
__device__ float g_m[N_NODES * KH];
__device__ float g_s[N_NODES * KH];

// ---------------- helpers ----------------
__device__ __forceinline__ void atomicMaxF(float* addr, float v) {
    // max over floats with possible negatives; init must be -inf.
    if (v >= 0.0f) atomicMax((int*)addr, __float_as_int(v));
    else           atomicMin((unsigned int*)addr, __float_as_uint(v));
}

// ---------------- P0: init out, m, s ----------------
__global__ void init_kernel(float* __restrict__ out) {
    int tid = blockIdx.x * blockDim.x + threadIdx.x;
    if (tid < N_NODES * F) out[tid] = 0.0f;
    if (tid < N_NODES * KH) {
        g_m[tid] = -__int_as_float(0x7f800000);  // -inf
        g_s[tid] = 0.0f;
    }
}

// ---------------- P1: feat @ W -> g_feat_src ----------------
// 64 rows per block, 256 threads, k-tiles of 32.
#define BM 64
#define BK 32
__global__ __launch_bounds__(256) void gemm_kernel(const float* __restrict__ feat,
                                                   const float* __restrict__ W) {
    __shared__ float sXT[BK][BM + 1];   // transposed X tile (pad to kill conflicts)
    __shared__ float sW[BK][F];         // W tile
    const int row0 = blockIdx.x * BM;
    const int t  = threadIdx.x;
    const int tx = t & 31;   // col group: cols tx*4 .. tx*4+3
    const int ty = t >> 5;   // row group: rows ty*8 .. ty*8+7

    float acc[8][4];
#pragma unroll
    for (int r = 0; r < 8; r++)
#pragma unroll
        for (int c = 0; c < 4; c++) acc[r][c] = 0.0f;

    for (int k0 = 0; k0 < IN_DIM; k0 += BK) {
        // load X tile: 64 rows x 32 cols = 512 float4, 2 per thread
#pragma unroll
        for (int i = 0; i < 2; i++) {
            int idx = t + i * 256;          // 0..511
            int r   = idx >> 3;             // 0..63
            int c4  = idx & 7;              // 0..7
            float4 v = make_float4(0.f, 0.f, 0.f, 0.f);
            int gr = row0 + r;
            if (gr < N_NODES) v = *(const float4*)&feat[gr * IN_DIM + k0 + c4 * 4];
            sXT[c4 * 4 + 0][r] = v.x;
            sXT[c4 * 4 + 1][r] = v.y;
            sXT[c4 * 4 + 2][r] = v.z;
            sXT[c4 * 4 + 3][r] = v.w;
        }
        // load W tile: 32 rows x 128 cols = 1024 float4, 4 per thread
#pragma unroll
        for (int i = 0; i < 4; i++) {
            int idx = t + i * 256;          // 0..1023
            int r   = idx >> 5;             // 0..31
            int c4  = idx & 31;             // 0..31
            *(float4*)&sW[r][c4 * 4] = *(const float4*)&W[(k0 + r) * F + c4 * 4];
        }
        __syncthreads();
#pragma unroll
        for (int kk = 0; kk < BK; kk++) {
            float4 wv = *(const float4*)&sW[kk][tx * 4];
            float xr[8];
#pragma unroll
            for (int r = 0; r < 8; r++) xr[r] = sXT[kk][ty * 8 + r];
#pragma unroll
            for (int r = 0; r < 8; r++) {
                acc[r][0] = fmaf(xr[r], wv.x, acc[r][0]);
                acc[r][1] = fmaf(xr[r], wv.y, acc[r][1]);
                acc[r][2] = fmaf(xr[r], wv.z, acc[r][2]);
                acc[r][3] = fmaf(xr[r], wv.w, acc[r][3]);
            }
        }
        __syncthreads();
    }
#pragma unroll
    for (int r = 0; r < 8; r++) {
        int gr = row0 + ty * 8 + r;
        if (gr < N_NODES) {
            float4 v = make_float4(acc[r][0], acc[r][1], acc[r][2], acc[r][3]);
            *(float4*)&g_feat_src[gr * F + tx * 4] = v;
        }
    }
}

// ---------------- P1b: el/er per (node, head) ----------------
__global__ void elr_kernel(const float* __restrict__ attn_l,
                           const float* __restrict__ attn_r) {
    int tid = blockIdx.x * blockDim.x + threadIdx.x;
    if (tid >= N_NODES * KH) return;
    int n = tid >> 3;
    int k = tid & 7;
    const float* row = &g_feat_src[n * F + k * DH];
    const float* al  = &attn_l[k * DH];
    const float* ar  = &attn_r[k * DH];
    float sl = 0.f, sr = 0.f;
#pragma unroll
    for (int j = 0; j < DH; j += 4) {
        float4 h = *(const float4*)&row[j];
        float4 a = *(const float4*)&al[j];
        float4 b = *(const float4*)&ar[j];
        sl += h.x * a.x + h.y * a.y + h.z * a.z + h.w * a.w;
        sr += h.x * b.x + h.y * b.y + h.z * b.z + h.w * b.w;
    }
    g_el[tid] = sl;
    g_er[tid] = sr;
}

// ---------------- P2: edge logits + segment max ----------------
__global__ void edge_logit_kernel(const int* __restrict__ src,
                                  const int* __restrict__ dst) {
    int tid = blockIdx.x * blockDim.x + threadIdx.x;
    if (tid >= E_EDGES * KH) return;
    int e = tid >> 3;
    int k = tid & 7;
    int s = src[e];
    int d = dst[e];
    float v = g_el[s * KH + k] + g_er[d * KH + k];
    v = (v > 0.0f) ? v : NEG_SLOPE * v;   // leaky relu
    g_e[tid] = v;
    atomicMaxF(&g_m[d * KH + k], v);
}

// ---------------- P3: exp + segment sum ----------------
__global__ void edge_exp_kernel(const int* __restrict__ dst) {
    int tid = blockIdx.x * blockDim.x + threadIdx.x;
    if (tid >= E_EDGES * KH) return;
    int e = tid >> 3;
    int k = tid & 7;
    int d = dst[e];
    float ex = __expf(g_e[tid] - g_m[d * KH + k]);
    g_e[tid] = ex;
    atomicAdd(&g_s[d * KH + k], ex);
}

// ---------------- P4: warp-per-edge weighted scatter-add ----------------
__global__ __launch_bounds__(256) void agg_kernel(const int* __restrict__ src,
                                                  const int* __restrict__ dst,
                                                  float* __restrict__ out) {
    int gtid = blockIdx.x * blockDim.x + threadIdx.x;
    int w    = gtid >> 5;          // edge id
    int lane = gtid & 31;
    if (w >= E_EDGES) return;
    int s = src[w];
    int d = dst[w];
    int k = lane >> 2;             // head for this lane's 4 floats
    float ex = g_e[w * KH + k];
    float sm = g_s[d * KH + k];
    float a  = __fdividef(ex, sm);
    float4 v = *(const float4*)&g_feat_src[s * F + lane * 4];
    float4 r = make_float4(v.x * a, v.y * a, v.z * a, v.w * a);
    float* p = &out[d * F + lane * 4];
    asm volatile("red.global.add.v4.f32 [%0], {%1,%2,%3,%4};"
                 :: "l"(p), "f"(r.x), "f"(r.y), "f"(r.z), "f"(r.w)
                 : "memory");
}

// ---------------- launch ----------------
extern "C" void kernel_launch(void* const* d_in, const int* in_sizes, int n_in,
                              void* d_out, int out_size) {
    const float* feat   = (const float*)d_in[0];
    const float* W      = (const float*)d_in[1];
    const float* attn_l = (const float*)d_in[2];
    const float* attn_r = (const float*)d_in[3];
    const int*   src    = (const int*)d_in[4];
    const int*   dst    = (const int*)d_in[5];
    float* out = (float*)d_out;

    const int threads = 256;
    int init_grid = (N_NODES * F + threads - 1) / threads;          // covers out + m/s
    init_kernel<<<init_grid, threads>>>(out);

    int gemm_grid = (N_NODES + BM - 1) / BM;                        // 1563
    gemm_kernel<<<gemm_grid, threads>>>(feat, W);

    int elr_grid = (N_NODES * KH + threads - 1) / threads;
    elr_kernel<<<elr_grid, threads>>>(attn_l, attn_r);

    int edge_grid = (E_EDGES * KH + threads - 1) / threads;         // 50000
    edge_logit_kernel<<<edge_grid, threads>>>(src, dst);
    edge_exp_kernel<<<edge_grid, threads>>>(dst);

    int agg_grid = (E_EDGES * 32 + threads - 1) / threads;          // 200000
    agg_kernel<<<agg_grid, threads>>>(src, dst, out);
}

// round 2
// speedup vs baseline: 1.2799x; 1.2799x over previous
#include <cuda_runtime.h>
#include <cuda_fp16.h>

#define N_NODES 100000
#define E_EDGES 1600000
#define IN_DIM  128
#define KH      8
#define DH      16
#define F       128          // KH*DH
#define NEG_SLOPE 0.2f

// ---------------- scratch (device globals; allocation-free) ----------------
__device__ float  g_feat_src[N_NODES * F];   // 51.2 MB fp32 (for elr; exactness)
__device__ __half g_feat_h[N_NODES * F];     // 25.6 MB fp16 copy (for agg gather)
__device__ float  g_el[N_NODES * KH];
__device__ float  g_er[N_NODES * KH];
__device__ float  g_s[N_NODES * KH];

// ---------------- P0: init out + s ----------------
__global__ void init_kernel(float* __restrict__ out) {
    int tid = blockIdx.x * blockDim.x + threadIdx.x;
    if (tid < N_NODES * F) out[tid] = 0.0f;
    if (tid < N_NODES * KH) g_s[tid] = 0.0f;
}

// ---------------- P1: feat @ W -> g_feat_src (+ fp16 copy), FFMA2 ----------
#define BM 64
#define BK 32
__global__ __launch_bounds__(256) void gemm_kernel(const float* __restrict__ feat,
                                                   const float* __restrict__ W) {
    __shared__ float sXT[BK][BM + 1];
    __shared__ float sW[BK][F];
    const int row0 = blockIdx.x * BM;
    const int t  = threadIdx.x;
    const int tx = t & 31;   // cols tx*4 .. tx*4+3
    const int ty = t >> 5;   // rows ty*8 .. ty*8+7

    unsigned long long acc2[8][2];
#pragma unroll
    for (int r = 0; r < 8; r++) { acc2[r][0] = 0ULL; acc2[r][1] = 0ULL; }

    for (int k0 = 0; k0 < IN_DIM; k0 += BK) {
#pragma unroll
        for (int i = 0; i < 2; i++) {
            int idx = t + i * 256;
            int r   = idx >> 3;
            int c4  = idx & 7;
            float4 v = make_float4(0.f, 0.f, 0.f, 0.f);
            int gr = row0 + r;
            if (gr < N_NODES) v = *(const float4*)&feat[gr * IN_DIM + k0 + c4 * 4];
            sXT[c4 * 4 + 0][r] = v.x;
            sXT[c4 * 4 + 1][r] = v.y;
            sXT[c4 * 4 + 2][r] = v.z;
            sXT[c4 * 4 + 3][r] = v.w;
        }
#pragma unroll
        for (int i = 0; i < 4; i++) {
            int idx = t + i * 256;
            int r   = idx >> 5;
            int c4  = idx & 31;
            *(float4*)&sW[r][c4 * 4] = *(const float4*)&W[(k0 + r) * F + c4 * 4];
        }
        __syncthreads();
#pragma unroll
        for (int kk = 0; kk < BK; kk++) {
            float4 wv = *(const float4*)&sW[kk][tx * 4];
            unsigned long long w01, w23;
            asm("mov.b64 %0, {%1, %2};" : "=l"(w01) : "f"(wv.x), "f"(wv.y));
            asm("mov.b64 %0, {%1, %2};" : "=l"(w23) : "f"(wv.z), "f"(wv.w));
#pragma unroll
            for (int r = 0; r < 8; r++) {
                float x = sXT[kk][ty * 8 + r];
                unsigned long long x2;
                asm("mov.b64 %0, {%1, %1};" : "=l"(x2) : "f"(x));
                asm("fma.rn.f32x2 %0, %1, %2, %3;"
                    : "=l"(acc2[r][0]) : "l"(x2), "l"(w01), "l"(acc2[r][0]));
                asm("fma.rn.f32x2 %0, %1, %2, %3;"
                    : "=l"(acc2[r][1]) : "l"(x2), "l"(w23), "l"(acc2[r][1]));
            }
        }
        __syncthreads();
    }
#pragma unroll
    for (int r = 0; r < 8; r++) {
        int gr = row0 + ty * 8 + r;
        if (gr < N_NODES) {
            float a0, a1, a2, a3;
            asm("mov.b64 {%0, %1}, %2;" : "=f"(a0), "=f"(a1) : "l"(acc2[r][0]));
            asm("mov.b64 {%0, %1}, %2;" : "=f"(a2), "=f"(a3) : "l"(acc2[r][1]));
            *(float4*)&g_feat_src[gr * F + tx * 4] = make_float4(a0, a1, a2, a3);
            __half2* hp = (__half2*)&g_feat_h[gr * F + tx * 4];
            hp[0] = __floats2half2_rn(a0, a1);
            hp[1] = __floats2half2_rn(a2, a3);
        }
    }
}

// ---------------- P1b: el/er per (node, head) ----------------
__global__ void elr_kernel(const float* __restrict__ attn_l,
                           const float* __restrict__ attn_r) {
    int tid = blockIdx.x * blockDim.x + threadIdx.x;
    if (tid >= N_NODES * KH) return;
    int n = tid >> 3;
    int k = tid & 7;
    const float* row = &g_feat_src[n * F + k * DH];
    const float* al  = &attn_l[k * DH];
    const float* ar  = &attn_r[k * DH];
    float sl = 0.f, sr = 0.f;
#pragma unroll
    for (int j = 0; j < DH; j += 4) {
        float4 h = *(const float4*)&row[j];
        float4 a = *(const float4*)&al[j];
        float4 b = *(const float4*)&ar[j];
        sl += h.x * a.x + h.y * a.y + h.z * a.z + h.w * a.w;
        sr += h.x * b.x + h.y * b.y + h.z * b.z + h.w * b.w;
    }
    g_el[tid] = sl;
    g_er[tid] = sr;
}

// ---------------- P2: per-edge exp + segment sum (no max shift) -----------
// exp(e - m)/sum(exp(e - m)) == exp(e)/sum(exp(e)); logits are O(3), safe.
__global__ void edge_sum_kernel(const int* __restrict__ src,
                                const int* __restrict__ dst) {
    int tid = blockIdx.x * blockDim.x + threadIdx.x;
    if (tid >= E_EDGES * KH) return;
    int e = tid >> 3;
    int k = tid & 7;
    int s = src[e];
    int d = dst[e];
    float v = g_el[s * KH + k] + g_er[d * KH + k];
    v = (v > 0.0f) ? v : NEG_SLOPE * v;
    atomicAdd(&g_s[d * KH + k], __expf(v));
}

// ---------------- P3: warp-per-edge weighted scatter-add ------------------
__global__ __launch_bounds__(256) void agg_kernel(const int* __restrict__ src,
                                                  const int* __restrict__ dst,
                                                  float* __restrict__ out) {
    int gtid = blockIdx.x * blockDim.x + threadIdx.x;
    int w    = gtid >> 5;          // edge id
    int lane = gtid & 31;
    if (w >= E_EDGES) return;
    int s = src[w];
    int d = dst[w];
    int k = lane >> 2;             // head for this lane's 4 values
    float v = g_el[s * KH + k] + g_er[d * KH + k];
    v = (v > 0.0f) ? v : NEG_SLOPE * v;
    float ex = __expf(v);
    float a  = __fdividef(ex, g_s[d * KH + k]);
    const __half2* hp = (const __half2*)&g_feat_h[s * F + lane * 4];
    __half2 h0 = hp[0], h1 = hp[1];
    float2 f0 = __half22float2(h0);
    float2 f1 = __half22float2(h1);
    float* p = &out[d * F + lane * 4];
    asm volatile("red.global.add.v4.f32 [%0], {%1,%2,%3,%4};"
                 :: "l"(p), "f"(f0.x * a), "f"(f0.y * a), "f"(f1.x * a), "f"(f1.y * a)
                 : "memory");
}

// ---------------- launch ----------------
extern "C" void kernel_launch(void* const* d_in, const int* in_sizes, int n_in,
                              void* d_out, int out_size) {
    const float* feat   = (const float*)d_in[0];
    const float* W      = (const float*)d_in[1];
    const float* attn_l = (const float*)d_in[2];
    const float* attn_r = (const float*)d_in[3];
    const int*   src    = (const int*)d_in[4];
    const int*   dst    = (const int*)d_in[5];
    float* out = (float*)d_out;

    const int threads = 256;
    int init_grid = (N_NODES * F + threads - 1) / threads;
    init_kernel<<<init_grid, threads>>>(out);

    int gemm_grid = (N_NODES + BM - 1) / BM;
    gemm_kernel<<<gemm_grid, threads>>>(feat, W);

    int elr_grid = (N_NODES * KH + threads - 1) / threads;
    elr_kernel<<<elr_grid, threads>>>(attn_l, attn_r);

    int edge_grid = (E_EDGES * KH + threads - 1) / threads;
    edge_sum_kernel<<<edge_grid, threads>>>(src, dst);

    int agg_grid = (E_EDGES * 32 + threads - 1) / threads;
    agg_kernel<<<agg_grid, threads>>>(src, dst, out);
}

// round 3
// speedup vs baseline: 2.1132x; 1.6510x over previous
#include <cuda_runtime.h>
#include <cuda_fp16.h>

#define N_NODES 100000
#define E_EDGES 1600000
#define IN_DIM  128
#define KH      8
#define DH      16
#define F       128
#define NEG_SLOPE 0.2f
#define SCAN_B  1024
#define NBLK    ((N_NODES + SCAN_B - 1) / SCAN_B)   // 98

// ---------------- scratch ----------------
__device__ float  g_feat_src[N_NODES * F];
__device__ __half g_feat_h[N_NODES * F];
__device__ float  g_el[N_NODES * KH];
__device__ float  g_er[N_NODES * KH];
__device__ int    g_deg[N_NODES];
__device__ int    g_off[N_NODES + 1];
__device__ int    g_cursor[N_NODES];
__device__ int    g_bsum[128];
__device__ int    g_psrc[E_EDGES];

// ---------------- P0: zero deg ----------------
__global__ void init_kernel() {
    int tid = blockIdx.x * blockDim.x + threadIdx.x;
    if (tid < N_NODES) g_deg[tid] = 0;
    if (tid < 128) g_bsum[tid] = 0;
}

// ---------------- P1: GEMM feat @ W (FFMA2) ----------------
#define BM 64
#define BK 32
__global__ __launch_bounds__(256) void gemm_kernel(const float* __restrict__ feat,
                                                   const float* __restrict__ W) {
    __shared__ float sXT[BK][BM + 1];
    __shared__ float sW[BK][F];
    const int row0 = blockIdx.x * BM;
    const int t  = threadIdx.x;
    const int tx = t & 31;
    const int ty = t >> 5;

    unsigned long long acc2[8][2];
#pragma unroll
    for (int r = 0; r < 8; r++) { acc2[r][0] = 0ULL; acc2[r][1] = 0ULL; }

    for (int k0 = 0; k0 < IN_DIM; k0 += BK) {
#pragma unroll
        for (int i = 0; i < 2; i++) {
            int idx = t + i * 256;
            int r   = idx >> 3;
            int c4  = idx & 7;
            float4 v = make_float4(0.f, 0.f, 0.f, 0.f);
            int gr = row0 + r;
            if (gr < N_NODES) v = *(const float4*)&feat[gr * IN_DIM + k0 + c4 * 4];
            sXT[c4 * 4 + 0][r] = v.x;
            sXT[c4 * 4 + 1][r] = v.y;
            sXT[c4 * 4 + 2][r] = v.z;
            sXT[c4 * 4 + 3][r] = v.w;
        }
#pragma unroll
        for (int i = 0; i < 4; i++) {
            int idx = t + i * 256;
            int r   = idx >> 5;
            int c4  = idx & 31;
            *(float4*)&sW[r][c4 * 4] = *(const float4*)&W[(k0 + r) * F + c4 * 4];
        }
        __syncthreads();
#pragma unroll
        for (int kk = 0; kk < BK; kk++) {
            float4 wv = *(const float4*)&sW[kk][tx * 4];
            unsigned long long w01, w23;
            asm("mov.b64 %0, {%1, %2};" : "=l"(w01) : "f"(wv.x), "f"(wv.y));
            asm("mov.b64 %0, {%1, %2};" : "=l"(w23) : "f"(wv.z), "f"(wv.w));
#pragma unroll
            for (int r = 0; r < 8; r++) {
                float x = sXT[kk][ty * 8 + r];
                unsigned long long x2;
                asm("mov.b64 %0, {%1, %1};" : "=l"(x2) : "f"(x));
                asm("fma.rn.f32x2 %0, %1, %2, %3;"
                    : "=l"(acc2[r][0]) : "l"(x2), "l"(w01), "l"(acc2[r][0]));
                asm("fma.rn.f32x2 %0, %1, %2, %3;"
                    : "=l"(acc2[r][1]) : "l"(x2), "l"(w23), "l"(acc2[r][1]));
            }
        }
        __syncthreads();
    }
#pragma unroll
    for (int r = 0; r < 8; r++) {
        int gr = row0 + ty * 8 + r;
        if (gr < N_NODES) {
            float a0, a1, a2, a3;
            asm("mov.b64 {%0, %1}, %2;" : "=f"(a0), "=f"(a1) : "l"(acc2[r][0]));
            asm("mov.b64 {%0, %1}, %2;" : "=f"(a2), "=f"(a3) : "l"(acc2[r][1]));
            *(float4*)&g_feat_src[gr * F + tx * 4] = make_float4(a0, a1, a2, a3);
            __half2* hp = (__half2*)&g_feat_h[gr * F + tx * 4];
            hp[0] = __floats2half2_rn(a0, a1);
            hp[1] = __floats2half2_rn(a2, a3);
        }
    }
}

// ---------------- P2: el/er ----------------
__global__ void elr_kernel(const float* __restrict__ attn_l,
                           const float* __restrict__ attn_r) {
    int tid = blockIdx.x * blockDim.x + threadIdx.x;
    if (tid >= N_NODES * KH) return;
    int n = tid >> 3;
    int k = tid & 7;
    const float* row = &g_feat_src[n * F + k * DH];
    const float* al  = &attn_l[k * DH];
    const float* ar  = &attn_r[k * DH];
    float sl = 0.f, sr = 0.f;
#pragma unroll
    for (int j = 0; j < DH; j += 4) {
        float4 h = *(const float4*)&row[j];
        float4 a = *(const float4*)&al[j];
        float4 b = *(const float4*)&ar[j];
        sl += h.x * a.x + h.y * a.y + h.z * a.z + h.w * a.w;
        sr += h.x * b.x + h.y * b.y + h.z * b.z + h.w * b.w;
    }
    g_el[tid] = sl;
    g_er[tid] = sr;
}

// ---------------- CSR build ----------------
__global__ void hist_kernel(const int* __restrict__ dst) {
    int e = blockIdx.x * blockDim.x + threadIdx.x;
    if (e < E_EDGES) atomicAdd(&g_deg[dst[e]], 1);
}

__global__ __launch_bounds__(SCAN_B) void scanA_kernel() {
    __shared__ int sm[SCAN_B];
    int tid = threadIdx.x;
    int gid = blockIdx.x * SCAN_B + tid;
    int v = (gid < N_NODES) ? g_deg[gid] : 0;
    sm[tid] = v;
    __syncthreads();
#pragma unroll
    for (int d = 1; d < SCAN_B; d <<= 1) {
        int t = (tid >= d) ? sm[tid - d] : 0;
        __syncthreads();
        sm[tid] += t;
        __syncthreads();
    }
    if (gid < N_NODES) g_off[gid] = sm[tid] - v;     // exclusive, block-local
    if (tid == SCAN_B - 1) g_bsum[blockIdx.x] = sm[tid];
}

__global__ __launch_bounds__(128) void scanB_kernel() {
    __shared__ int sm[128];
    int tid = threadIdx.x;
    int v = (tid < NBLK) ? g_bsum[tid] : 0;
    sm[tid] = v;
    __syncthreads();
#pragma unroll
    for (int d = 1; d < 128; d <<= 1) {
        int t = (tid >= d) ? sm[tid - d] : 0;
        __syncthreads();
        sm[tid] += t;
        __syncthreads();
    }
    g_bsum[tid] = sm[tid] - v;                       // exclusive
}

__global__ void scanC_kernel() {
    int gid = blockIdx.x * blockDim.x + threadIdx.x;
    if (gid < N_NODES) {
        int off = g_off[gid] + g_bsum[gid >> 10];
        g_off[gid] = off;
        g_cursor[gid] = off;
    }
    if (gid == 0) g_off[N_NODES] = E_EDGES;
}

__global__ void scatter_kernel(const int* __restrict__ src,
                               const int* __restrict__ dst) {
    int e = blockIdx.x * blockDim.x + threadIdx.x;
    if (e >= E_EDGES) return;
    int pos = atomicAdd(&g_cursor[dst[e]], 1);
    g_psrc[pos] = src[e];
}

// ---------------- P3: warp-per-dst gather aggregation ----------------
__global__ __launch_bounds__(256) void agg_csr_kernel(float* __restrict__ out) {
    int w    = (blockIdx.x * blockDim.x + threadIdx.x) >> 5;
    int lane = threadIdx.x & 31;
    if (w >= N_NODES) return;
    int off0 = g_off[w];
    int off1 = g_off[w + 1];
    int deg  = off1 - off0;

    float er_l = (lane < 8) ? g_er[w * KH + lane] : 0.f;
    int khead = lane >> 2;                              // head for pass2 lane
    float er_k = __shfl_sync(0xffffffffu, er_l, khead);

    // pass 1: softmax denominator. 4 edges/iter, 8 lanes per edge (one per head)
    int grp = lane >> 3;                                // 0..3 edge slot
    int kk  = lane & 7;                                 // head
    float er_kk = __shfl_sync(0xffffffffu, er_l, kk);
    float ssum = 0.f;
    for (int i = off0 + grp; i < off1; i += 4) {
        int s = g_psrc[i];
        float v = g_el[s * KH + kk] + er_kk;
        v = (v > 0.f) ? v : NEG_SLOPE * v;
        ssum += __expf(v);
    }
    ssum += __shfl_xor_sync(0xffffffffu, ssum, 8);
    ssum += __shfl_xor_sync(0xffffffffu, ssum, 16);     // lane l: total for head l&7
    float s_k = __shfl_sync(0xffffffffu, ssum, khead);
    float inv = (deg > 0) ? __fdividef(1.f, s_k) : 0.f;

    // pass 2: weighted accumulation, lane covers features lane*4..lane*4+3
    float4 acc = make_float4(0.f, 0.f, 0.f, 0.f);
    for (int i = off0; i < off1; i++) {
        int s = g_psrc[i];
        float v = g_el[s * KH + khead] + er_k;
        v = (v > 0.f) ? v : NEG_SLOPE * v;
        float a = __expf(v) * inv;
        const __half2* hp = (const __half2*)&g_feat_h[s * F + lane * 4];
        float2 f0 = __half22float2(hp[0]);
        float2 f1 = __half22float2(hp[1]);
        acc.x = fmaf(a, f0.x, acc.x);
        acc.y = fmaf(a, f0.y, acc.y);
        acc.z = fmaf(a, f1.x, acc.z);
        acc.w = fmaf(a, f1.y, acc.w);
    }
    *(float4*)&out[w * F + lane * 4] = acc;
}

// ---------------- launch ----------------
extern "C" void kernel_launch(void* const* d_in, const int* in_sizes, int n_in,
                              void* d_out, int out_size) {
    const float* feat   = (const float*)d_in[0];
    const float* W      = (const float*)d_in[1];
    const float* attn_l = (const float*)d_in[2];
    const float* attn_r = (const float*)d_in[3];
    const int*   src    = (const int*)d_in[4];
    const int*   dst    = (const int*)d_in[5];
    float* out = (float*)d_out;

    const int T = 256;
    init_kernel<<<(N_NODES + T - 1) / T, T>>>();
    gemm_kernel<<<(N_NODES + BM - 1) / BM, T>>>(feat, W);
    elr_kernel<<<(N_NODES * KH + T - 1) / T, T>>>(attn_l, attn_r);
    hist_kernel<<<(E_EDGES + T - 1) / T, T>>>(dst);
    scanA_kernel<<<NBLK, SCAN_B>>>();
    scanB_kernel<<<1, 128>>>();
    scanC_kernel<<<(N_NODES + T - 1) / T, T>>>();
    scatter_kernel<<<(E_EDGES + T - 1) / T, T>>>(src, dst);
    agg_csr_kernel<<<(N_NODES * 32 + T - 1) / T, T>>>(out);
}

// round 4
// speedup vs baseline: 2.4252x; 1.1477x over previous
#include <cuda_runtime.h>
#include <cuda_fp16.h>

#define N_NODES 100000
#define E_EDGES 1600000
#define IN_DIM  128
#define KH      8
#define DH      16
#define F       128
#define NEG_SLOPE 0.2f
#define SCAN_B  1024
#define NBLK    ((N_NODES + SCAN_B - 1) / SCAN_B)   // 98
#define CAP     96                                   // cached edges per node

// ---------------- scratch ----------------
__device__ __half g_feat_h[N_NODES * F];     // 25.6 MB fp16 features
__device__ float  g_el[N_NODES * KH];
__device__ float  g_er[N_NODES * KH];
__device__ int    g_deg[N_NODES];
__device__ int    g_off[N_NODES + 1];
__device__ int    g_cursor[N_NODES];
__device__ int    g_bsum[128];
__device__ int    g_psrc[E_EDGES];

// ---------------- P0: zero deg ----------------
__global__ void init_kernel() {
    int tid = blockIdx.x * blockDim.x + threadIdx.x;
    if (tid < N_NODES) g_deg[tid] = 0;
    if (tid < 128) g_bsum[tid] = 0;
}

// ---------------- P1: GEMM feat @ W (FFMA2) + fused el/er ----------------
#define BM 64
#define BK 32
__global__ __launch_bounds__(256) void gemm_kernel(const float* __restrict__ feat,
                                                   const float* __restrict__ W,
                                                   const float* __restrict__ attn_l,
                                                   const float* __restrict__ attn_r) {
    __shared__ float sXT[BK][BM + 1];
    __shared__ float sW[BK][F];
    const int row0 = blockIdx.x * BM;
    const int t  = threadIdx.x;
    const int tx = t & 31;   // lane; cols tx*4 .. tx*4+3
    const int ty = t >> 5;   // rows ty*8 .. ty*8+7
    const int head = tx >> 2;
    const int sub  = tx & 3;

    // attention coefficients for this lane's 4 columns
    float4 al = *(const float4*)&attn_l[head * DH + sub * 4];
    float4 ar = *(const float4*)&attn_r[head * DH + sub * 4];

    unsigned long long acc2[8][2];
#pragma unroll
    for (int r = 0; r < 8; r++) { acc2[r][0] = 0ULL; acc2[r][1] = 0ULL; }

    for (int k0 = 0; k0 < IN_DIM; k0 += BK) {
#pragma unroll
        for (int i = 0; i < 2; i++) {
            int idx = t + i * 256;
            int r   = idx >> 3;
            int c4  = idx & 7;
            float4 v = make_float4(0.f, 0.f, 0.f, 0.f);
            int gr = row0 + r;
            if (gr < N_NODES) v = *(const float4*)&feat[gr * IN_DIM + k0 + c4 * 4];
            sXT[c4 * 4 + 0][r] = v.x;
            sXT[c4 * 4 + 1][r] = v.y;
            sXT[c4 * 4 + 2][r] = v.z;
            sXT[c4 * 4 + 3][r] = v.w;
        }
#pragma unroll
        for (int i = 0; i < 4; i++) {
            int idx = t + i * 256;
            int r   = idx >> 5;
            int c4  = idx & 31;
            *(float4*)&sW[r][c4 * 4] = *(const float4*)&W[(k0 + r) * F + c4 * 4];
        }
        __syncthreads();
#pragma unroll
        for (int kk = 0; kk < BK; kk++) {
            float4 wv = *(const float4*)&sW[kk][tx * 4];
            unsigned long long w01, w23;
            asm("mov.b64 %0, {%1, %2};" : "=l"(w01) : "f"(wv.x), "f"(wv.y));
            asm("mov.b64 %0, {%1, %2};" : "=l"(w23) : "f"(wv.z), "f"(wv.w));
#pragma unroll
            for (int r = 0; r < 8; r++) {
                float x = sXT[kk][ty * 8 + r];
                unsigned long long x2;
                asm("mov.b64 %0, {%1, %1};" : "=l"(x2) : "f"(x));
                asm("fma.rn.f32x2 %0, %1, %2, %3;"
                    : "=l"(acc2[r][0]) : "l"(x2), "l"(w01), "l"(acc2[r][0]));
                asm("fma.rn.f32x2 %0, %1, %2, %3;"
                    : "=l"(acc2[r][1]) : "l"(x2), "l"(w23), "l"(acc2[r][1]));
            }
        }
        __syncthreads();
    }
#pragma unroll
    for (int r = 0; r < 8; r++) {
        int gr = row0 + ty * 8 + r;
        float a0, a1, a2, a3;
        asm("mov.b64 {%0, %1}, %2;" : "=f"(a0), "=f"(a1) : "l"(acc2[r][0]));
        asm("mov.b64 {%0, %1}, %2;" : "=f"(a2), "=f"(a3) : "l"(acc2[r][1]));
        // partial dots for this lane's 4 columns of head `head`
        float pl = a0 * al.x + a1 * al.y + a2 * al.z + a3 * al.w;
        float pr = a0 * ar.x + a1 * ar.y + a2 * ar.z + a3 * ar.w;
        pl += __shfl_xor_sync(0xffffffffu, pl, 1);
        pl += __shfl_xor_sync(0xffffffffu, pl, 2);
        pr += __shfl_xor_sync(0xffffffffu, pr, 1);
        pr += __shfl_xor_sync(0xffffffffu, pr, 2);
        if (gr < N_NODES) {
            __half2* hp = (__half2*)&g_feat_h[gr * F + tx * 4];
            hp[0] = __floats2half2_rn(a0, a1);
            hp[1] = __floats2half2_rn(a2, a3);
            if (sub == 0) {
                g_el[gr * KH + head] = pl;
                g_er[gr * KH + head] = pr;
            }
        }
    }
}

// ---------------- CSR build ----------------
__global__ void hist_kernel(const int* __restrict__ dst) {
    int e = blockIdx.x * blockDim.x + threadIdx.x;
    if (e < E_EDGES) atomicAdd(&g_deg[dst[e]], 1);
}

__global__ __launch_bounds__(SCAN_B) void scanA_kernel() {
    __shared__ int sm[SCAN_B];
    int tid = threadIdx.x;
    int gid = blockIdx.x * SCAN_B + tid;
    int v = (gid < N_NODES) ? g_deg[gid] : 0;
    sm[tid] = v;
    __syncthreads();
#pragma unroll
    for (int d = 1; d < SCAN_B; d <<= 1) {
        int t = (tid >= d) ? sm[tid - d] : 0;
        __syncthreads();
        sm[tid] += t;
        __syncthreads();
    }
    if (gid < N_NODES) g_off[gid] = sm[tid] - v;
    if (tid == SCAN_B - 1) g_bsum[blockIdx.x] = sm[tid];
}

__global__ __launch_bounds__(128) void scanB_kernel() {
    __shared__ int sm[128];
    int tid = threadIdx.x;
    int v = (tid < NBLK) ? g_bsum[tid] : 0;
    sm[tid] = v;
    __syncthreads();
#pragma unroll
    for (int d = 1; d < 128; d <<= 1) {
        int t = (tid >= d) ? sm[tid - d] : 0;
        __syncthreads();
        sm[tid] += t;
        __syncthreads();
    }
    g_bsum[tid] = sm[tid] - v;
}

__global__ void scanC_kernel() {
    int gid = blockIdx.x * blockDim.x + threadIdx.x;
    if (gid < N_NODES) {
        int off = g_off[gid] + g_bsum[gid >> 10];
        g_off[gid] = off;
        g_cursor[gid] = off;
    }
    if (gid == 0) g_off[N_NODES] = E_EDGES;
}

__global__ void scatter_kernel(const int* __restrict__ src,
                               const int* __restrict__ dst) {
    int e = blockIdx.x * blockDim.x + threadIdx.x;
    if (e >= E_EDGES) return;
    int pos = atomicAdd(&g_cursor[dst[e]], 1);
    g_psrc[pos] = src[e];
}

// ---------------- P3: warp-per-dst gather, smem-staged weights ----------------
__global__ __launch_bounds__(256) void agg_csr_kernel(float* __restrict__ out) {
    __shared__ int   s_src[8][CAP];
    __shared__ float s_w[8][CAP][KH];
    int wid  = threadIdx.x >> 5;
    int lane = threadIdx.x & 31;
    int w = blockIdx.x * 8 + wid;
    if (w >= N_NODES) return;
    int off0 = g_off[w];
    int off1 = g_off[w + 1];
    int deg  = off1 - off0;
    int cached = (deg < CAP) ? deg : CAP;

    // cooperative psrc load
    for (int i = lane; i < cached; i += 32) s_src[wid][i] = g_psrc[off0 + i];
    __syncwarp();

    float er_l = (lane < 8) ? g_er[w * KH + lane] : 0.f;
    int kk  = lane & 7;
    int grp = lane >> 3;
    float er_kk = __shfl_sync(0xffffffffu, er_l, kk);

    // pass 1: denominators; stash exp weights in smem
    float ssum = 0.f;
    for (int i = grp; i < deg; i += 4) {
        int s = (i < cached) ? s_src[wid][i] : g_psrc[off0 + i];
        float v = g_el[s * KH + kk] + er_kk;
        v = (v > 0.f) ? v : NEG_SLOPE * v;
        float ex = __expf(v);
        if (i < CAP) s_w[wid][i][kk] = ex;
        ssum += ex;
    }
    ssum += __shfl_xor_sync(0xffffffffu, ssum, 8);
    ssum += __shfl_xor_sync(0xffffffffu, ssum, 16);
    int khead = lane >> 2;
    float s_k  = __shfl_sync(0xffffffffu, ssum, khead);
    float er_k = __shfl_sync(0xffffffffu, er_l, khead);
    float inv  = (deg > 0) ? __fdividef(1.f, s_k) : 0.f;
    __syncwarp();

    // pass 2: weighted gather, unroll 2
    float4 acc = make_float4(0.f, 0.f, 0.f, 0.f);
    int i = 0;
    for (; i + 1 < cached; i += 2) {
        int s0 = s_src[wid][i];
        int s1 = s_src[wid][i + 1];
        float a0 = s_w[wid][i][khead] * inv;
        float a1 = s_w[wid][i + 1][khead] * inv;
        const __half2* hp0 = (const __half2*)&g_feat_h[s0 * F + lane * 4];
        const __half2* hp1 = (const __half2*)&g_feat_h[s1 * F + lane * 4];
        __half2 p00 = hp0[0], p01 = hp0[1];
        __half2 p10 = hp1[0], p11 = hp1[1];
        float2 f00 = __half22float2(p00), f01 = __half22float2(p01);
        float2 f10 = __half22float2(p10), f11 = __half22float2(p11);
        acc.x = fmaf(a0, f00.x, fmaf(a1, f10.x, acc.x));
        acc.y = fmaf(a0, f00.y, fmaf(a1, f10.y, acc.y));
        acc.z = fmaf(a0, f01.x, fmaf(a1, f11.x, acc.z));
        acc.w = fmaf(a0, f01.y, fmaf(a1, f11.y, acc.w));
    }
    for (; i < cached; i++) {
        int s = s_src[wid][i];
        float a = s_w[wid][i][khead] * inv;
        const __half2* hp = (const __half2*)&g_feat_h[s * F + lane * 4];
        float2 f0 = __half22float2(hp[0]);
        float2 f1 = __half22float2(hp[1]);
        acc.x = fmaf(a, f0.x, acc.x);
        acc.y = fmaf(a, f0.y, acc.y);
        acc.z = fmaf(a, f1.x, acc.z);
        acc.w = fmaf(a, f1.y, acc.w);
    }
    for (; i < deg; i++) {   // fallback beyond CAP (recompute weight)
        int s = g_psrc[off0 + i];
        float v = g_el[s * KH + khead] + er_k;
        v = (v > 0.f) ? v : NEG_SLOPE * v;
        float a = __expf(v) * inv;
        const __half2* hp = (const __half2*)&g_feat_h[s * F + lane * 4];
        float2 f0 = __half22float2(hp[0]);
        float2 f1 = __half22float2(hp[1]);
        acc.x = fmaf(a, f0.x, acc.x);
        acc.y = fmaf(a, f0.y, acc.y);
        acc.z = fmaf(a, f1.x, acc.z);
        acc.w = fmaf(a, f1.y, acc.w);
    }
    *(float4*)&out[w * F + lane * 4] = acc;
}

// ---------------- launch ----------------
extern "C" void kernel_launch(void* const* d_in, const int* in_sizes, int n_in,
                              void* d_out, int out_size) {
    const float* feat   = (const float*)d_in[0];
    const float* W      = (const float*)d_in[1];
    const float* attn_l = (const float*)d_in[2];
    const float* attn_r = (const float*)d_in[3];
    const int*   src    = (const int*)d_in[4];
    const int*   dst    = (const int*)d_in[5];
    float* out = (float*)d_out;

    const int T = 256;
    init_kernel<<<(N_NODES + T - 1) / T, T>>>();
    gemm_kernel<<<(N_NODES + BM - 1) / BM, T>>>(feat, W, attn_l, attn_r);
    hist_kernel<<<(E_EDGES + T - 1) / T, T>>>(dst);
    scanA_kernel<<<NBLK, SCAN_B>>>();
    scanB_kernel<<<1, 128>>>();
    scanC_kernel<<<(N_NODES + T - 1) / T, T>>>();
    scatter_kernel<<<(E_EDGES + T - 1) / T, T>>>(src, dst);
    agg_csr_kernel<<<(N_NODES + 7) / 8, T>>>(out);
}

// round 5
// speedup vs baseline: 2.6685x; 1.1003x over previous
#include <cuda_runtime.h>
#include <cuda_fp16.h>

#define N_NODES 100000
#define E_EDGES 1600000
#define IN_DIM  128
#define KH      8
#define DH      16
#define F       128
#define NEG_SLOPE 0.2f
#define SCAN_B  1024
#define NBLK    ((N_NODES + SCAN_B - 1) / SCAN_B)   // 98
#define CAP     96

// ---------------- scratch ----------------
__device__ __half g_feat_h[N_NODES * F];
__device__ float  g_el[N_NODES * KH];
__device__ float  g_er[N_NODES * KH];
__device__ int    g_deg[N_NODES];
__device__ int    g_off[N_NODES + 1];
__device__ int    g_cursor[N_NODES];
__device__ int    g_bsum[128];
__device__ int    g_psrc[E_EDGES];

// ---------------- P0: zero deg ----------------
__global__ void init_kernel() {
    int tid = blockIdx.x * blockDim.x + threadIdx.x;
    if (tid < N_NODES) g_deg[tid] = 0;
    if (tid < 128) g_bsum[tid] = 0;
}

// ---------------- P1: GEMM feat @ W (row-pair FFMA2) + fused el/er --------
#define BM 64
#define BK 32
__global__ __launch_bounds__(256) void gemm_kernel(const float* __restrict__ feat,
                                                   const float* __restrict__ W,
                                                   const float* __restrict__ attn_l,
                                                   const float* __restrict__ attn_r) {
    __shared__ __align__(16) float sXT[BK][BM + 4];   // stride 68 floats (16B-aligned)
    __shared__ __align__(16) float sW[BK][F];
    const int row0 = blockIdx.x * BM;
    const int t  = threadIdx.x;
    const int tx = t & 31;
    const int ty = t >> 5;
    const int head = tx >> 2;
    const int sub  = tx & 3;

    float4 al = *(const float4*)&attn_l[head * DH + sub * 4];
    float4 ar = *(const float4*)&attn_r[head * DH + sub * 4];

    // acc2[p][c] = {acc[row 2p][col c], acc[row 2p+1][col c]}
    unsigned long long acc2[4][4];
#pragma unroll
    for (int p = 0; p < 4; p++)
#pragma unroll
        for (int c = 0; c < 4; c++) acc2[p][c] = 0ULL;

    for (int k0 = 0; k0 < IN_DIM; k0 += BK) {
#pragma unroll
        for (int i = 0; i < 2; i++) {
            int idx = t + i * 256;
            int r   = idx >> 3;
            int c4  = idx & 7;
            float4 v = make_float4(0.f, 0.f, 0.f, 0.f);
            int gr = row0 + r;
            if (gr < N_NODES) v = *(const float4*)&feat[gr * IN_DIM + k0 + c4 * 4];
            sXT[c4 * 4 + 0][r] = v.x;
            sXT[c4 * 4 + 1][r] = v.y;
            sXT[c4 * 4 + 2][r] = v.z;
            sXT[c4 * 4 + 3][r] = v.w;
        }
#pragma unroll
        for (int i = 0; i < 4; i++) {
            int idx = t + i * 256;
            int r   = idx >> 5;
            int c4  = idx & 31;
            *(float4*)&sW[r][c4 * 4] = *(const float4*)&W[(k0 + r) * F + c4 * 4];
        }
        __syncthreads();
#pragma unroll
        for (int kk = 0; kk < BK; kk++) {
            float4 wv = *(const float4*)&sW[kk][tx * 4];
            float4 xa = *(const float4*)&sXT[kk][ty * 8];      // rows 0..3 (broadcast)
            float4 xb = *(const float4*)&sXT[kk][ty * 8 + 4];  // rows 4..7 (broadcast)
            unsigned long long xp[4], wd[4];
            asm("mov.b64 %0, {%1, %2};" : "=l"(xp[0]) : "f"(xa.x), "f"(xa.y));
            asm("mov.b64 %0, {%1, %2};" : "=l"(xp[1]) : "f"(xa.z), "f"(xa.w));
            asm("mov.b64 %0, {%1, %2};" : "=l"(xp[2]) : "f"(xb.x), "f"(xb.y));
            asm("mov.b64 %0, {%1, %2};" : "=l"(xp[3]) : "f"(xb.z), "f"(xb.w));
            asm("mov.b64 %0, {%1, %1};" : "=l"(wd[0]) : "f"(wv.x));
            asm("mov.b64 %0, {%1, %1};" : "=l"(wd[1]) : "f"(wv.y));
            asm("mov.b64 %0, {%1, %1};" : "=l"(wd[2]) : "f"(wv.z));
            asm("mov.b64 %0, {%1, %1};" : "=l"(wd[3]) : "f"(wv.w));
#pragma unroll
            for (int p = 0; p < 4; p++)
#pragma unroll
                for (int c = 0; c < 4; c++)
                    asm("fma.rn.f32x2 %0, %1, %2, %3;"
                        : "=l"(acc2[p][c]) : "l"(xp[p]), "l"(wd[c]), "l"(acc2[p][c]));
        }
        __syncthreads();
    }

    // unpack to accf[row][col]
    float accf[8][4];
#pragma unroll
    for (int p = 0; p < 4; p++)
#pragma unroll
        for (int c = 0; c < 4; c++)
            asm("mov.b64 {%0, %1}, %2;"
                : "=f"(accf[2 * p][c]), "=f"(accf[2 * p + 1][c]) : "l"(acc2[p][c]));

#pragma unroll
    for (int r = 0; r < 8; r++) {
        int gr = row0 + ty * 8 + r;
        float a0 = accf[r][0], a1 = accf[r][1], a2 = accf[r][2], a3 = accf[r][3];
        float pl = a0 * al.x + a1 * al.y + a2 * al.z + a3 * al.w;
        float pr = a0 * ar.x + a1 * ar.y + a2 * ar.z + a3 * ar.w;
        pl += __shfl_xor_sync(0xffffffffu, pl, 1);
        pl += __shfl_xor_sync(0xffffffffu, pl, 2);
        pr += __shfl_xor_sync(0xffffffffu, pr, 1);
        pr += __shfl_xor_sync(0xffffffffu, pr, 2);
        if (gr < N_NODES) {
            __half2* hp = (__half2*)&g_feat_h[gr * F + tx * 4];
            hp[0] = __floats2half2_rn(a0, a1);
            hp[1] = __floats2half2_rn(a2, a3);
            if (sub == 0) {
                g_el[gr * KH + head] = pl;
                g_er[gr * KH + head] = pr;
            }
        }
    }
}

// ---------------- CSR build ----------------
__global__ void hist_kernel(const int* __restrict__ dst) {
    int e = blockIdx.x * blockDim.x + threadIdx.x;
    if (e < E_EDGES) atomicAdd(&g_deg[dst[e]], 1);
}

__global__ __launch_bounds__(SCAN_B) void scanA_kernel() {
    __shared__ int sm[SCAN_B];
    int tid = threadIdx.x;
    int gid = blockIdx.x * SCAN_B + tid;
    int v = (gid < N_NODES) ? g_deg[gid] : 0;
    sm[tid] = v;
    __syncthreads();
#pragma unroll
    for (int d = 1; d < SCAN_B; d <<= 1) {
        int t = (tid >= d) ? sm[tid - d] : 0;
        __syncthreads();
        sm[tid] += t;
        __syncthreads();
    }
    if (gid < N_NODES) g_off[gid] = sm[tid] - v;
    if (tid == SCAN_B - 1) g_bsum[blockIdx.x] = sm[tid];
}

__global__ __launch_bounds__(128) void scanB_kernel() {
    __shared__ int sm[128];
    int tid = threadIdx.x;
    int v = (tid < NBLK) ? g_bsum[tid] : 0;
    sm[tid] = v;
    __syncthreads();
#pragma unroll
    for (int d = 1; d < 128; d <<= 1) {
        int t = (tid >= d) ? sm[tid - d] : 0;
        __syncthreads();
        sm[tid] += t;
        __syncthreads();
    }
    g_bsum[tid] = sm[tid] - v;
}

__global__ void scanC_kernel() {
    int gid = blockIdx.x * blockDim.x + threadIdx.x;
    if (gid < N_NODES) {
        int off = g_off[gid] + g_bsum[gid >> 10];
        g_off[gid] = off;
        g_cursor[gid] = off;
    }
    if (gid == 0) g_off[N_NODES] = E_EDGES;
}

__global__ void scatter_kernel(const int* __restrict__ src,
                               const int* __restrict__ dst) {
    int e = blockIdx.x * blockDim.x + threadIdx.x;
    if (e >= E_EDGES) return;
    int pos = atomicAdd(&g_cursor[dst[e]], 1);
    g_psrc[pos] = src[e];
}

// ---------------- P3: warp-per-dst gather ----------------
__device__ __forceinline__ void acc_edge(float4& acc, float a,
                                         unsigned long long pk) {
    __half2 h0 = ((const __half2*)&pk)[0];
    __half2 h1 = ((const __half2*)&pk)[1];
    float2 f0 = __half22float2(h0);
    float2 f1 = __half22float2(h1);
    acc.x = fmaf(a, f0.x, acc.x);
    acc.y = fmaf(a, f0.y, acc.y);
    acc.z = fmaf(a, f1.x, acc.z);
    acc.w = fmaf(a, f1.y, acc.w);
}

__global__ __launch_bounds__(256) void agg_csr_kernel(float* __restrict__ out) {
    __shared__ int   s_src[8][CAP];
    __shared__ float s_w[8][CAP][KH];
    int wid  = threadIdx.x >> 5;
    int lane = threadIdx.x & 31;
    int w = blockIdx.x * 8 + wid;
    if (w >= N_NODES) return;
    int off0 = g_off[w];
    int off1 = g_off[w + 1];
    int deg  = off1 - off0;
    int cached = (deg < CAP) ? deg : CAP;

    for (int i = lane; i < cached; i += 32) s_src[wid][i] = g_psrc[off0 + i];
    __syncwarp();

    float er_l = (lane < 8) ? g_er[w * KH + lane] : 0.f;
    int kk  = lane & 7;
    int grp = lane >> 3;
    float er_kk = __shfl_sync(0xffffffffu, er_l, kk);

    // pass 1: denominators + stash exp weights
    float ssum = 0.f;
    for (int i = grp; i < deg; i += 4) {
        int s = (i < cached) ? s_src[wid][i] : g_psrc[off0 + i];
        float v = g_el[s * KH + kk] + er_kk;
        v = (v > 0.f) ? v : NEG_SLOPE * v;
        float ex = __expf(v);
        if (i < CAP) s_w[wid][i][kk] = ex;
        ssum += ex;
    }
    ssum += __shfl_xor_sync(0xffffffffu, ssum, 8);
    ssum += __shfl_xor_sync(0xffffffffu, ssum, 16);
    int khead = lane >> 2;
    float s_k  = __shfl_sync(0xffffffffu, ssum, khead);
    float er_k = __shfl_sync(0xffffffffu, er_l, khead);
    float inv  = (deg > 0) ? __fdividef(1.f, s_k) : 0.f;
    __syncwarp();

    // pass 2: weighted gather, 8B vector loads, unroll 4
    float4 acc = make_float4(0.f, 0.f, 0.f, 0.f);
    int i = 0;
    for (; i + 3 < cached; i += 4) {
        int s0 = s_src[wid][i], s1 = s_src[wid][i + 1];
        int s2 = s_src[wid][i + 2], s3 = s_src[wid][i + 3];
        unsigned long long p0 = *(const unsigned long long*)&g_feat_h[s0 * F + lane * 4];
        unsigned long long p1 = *(const unsigned long long*)&g_feat_h[s1 * F + lane * 4];
        unsigned long long p2 = *(const unsigned long long*)&g_feat_h[s2 * F + lane * 4];
        unsigned long long p3 = *(const unsigned long long*)&g_feat_h[s3 * F + lane * 4];
        acc_edge(acc, s_w[wid][i][khead] * inv, p0);
        acc_edge(acc, s_w[wid][i + 1][khead] * inv, p1);
        acc_edge(acc, s_w[wid][i + 2][khead] * inv, p2);
        acc_edge(acc, s_w[wid][i + 3][khead] * inv, p3);
    }
    for (; i < cached; i++) {
        unsigned long long p = *(const unsigned long long*)&g_feat_h[s_src[wid][i] * F + lane * 4];
        acc_edge(acc, s_w[wid][i][khead] * inv, p);
    }
    for (; i < deg; i++) {   // beyond CAP: recompute weight
        int s = g_psrc[off0 + i];
        float v = g_el[s * KH + khead] + er_k;
        v = (v > 0.f) ? v : NEG_SLOPE * v;
        unsigned long long p = *(const unsigned long long*)&g_feat_h[s * F + lane * 4];
        acc_edge(acc, __expf(v) * inv, p);
    }
    *(float4*)&out[w * F + lane * 4] = acc;
}

// ---------------- launch (CSR chain overlapped with GEMM) ----------------
extern "C" void kernel_launch(void* const* d_in, const int* in_sizes, int n_in,
                              void* d_out, int out_size) {
    const float* feat   = (const float*)d_in[0];
    const float* W      = (const float*)d_in[1];
    const float* attn_l = (const float*)d_in[2];
    const float* attn_r = (const float*)d_in[3];
    const int*   src    = (const int*)d_in[4];
    const int*   dst    = (const int*)d_in[5];
    float* out = (float*)d_out;

    // one-time host resources (created on the non-captured correctness call)
    static cudaStream_t s2 = nullptr;
    static cudaEvent_t evFork = nullptr, evCsr = nullptr;
    if (s2 == nullptr) {
        cudaStreamCreateWithFlags(&s2, cudaStreamNonBlocking);
        cudaEventCreateWithFlags(&evFork, cudaEventDisableTiming);
        cudaEventCreateWithFlags(&evCsr, cudaEventDisableTiming);
    }

    const int T = 256;
    // fork: CSR chain on s2
    cudaEventRecord(evFork, 0);
    cudaStreamWaitEvent(s2, evFork, 0);
    init_kernel<<<(N_NODES + T - 1) / T, T, 0, s2>>>();
    hist_kernel<<<(E_EDGES + T - 1) / T, T, 0, s2>>>(dst);
    scanA_kernel<<<NBLK, SCAN_B, 0, s2>>>();
    scanB_kernel<<<1, 128, 0, s2>>>();
    scanC_kernel<<<(N_NODES + T - 1) / T, T, 0, s2>>>();
    scatter_kernel<<<(E_EDGES + T - 1) / T, T, 0, s2>>>(src, dst);
    cudaEventRecord(evCsr, s2);

    // GEMM concurrently on the origin stream
    gemm_kernel<<<(N_NODES + BM - 1) / BM, T>>>(feat, W, attn_l, attn_r);

    // join, then aggregate
    cudaStreamWaitEvent(0, evCsr, 0);
    agg_csr_kernel<<<(N_NODES + 7) / 8, T>>>(out);
}

// round 7
// speedup vs baseline: 2.6830x; 1.0054x over previous
#include <cuda_runtime.h>
#include <cuda_fp16.h>

#define N_NODES 100000
#define E_EDGES 1600000
#define IN_DIM  128
#define KH      8
#define DH      16
#define F       128
#define NEG_SLOPE 0.2f
#define SCAN_B  1024
#define NBLK    ((N_NODES + SCAN_B - 1) / SCAN_B)   // 98
#define CAP     128

// ---------------- scratch ----------------
__device__ __half g_feat_h[N_NODES * F];
__device__ float  g_el[N_NODES * KH];
__device__ float  g_er[N_NODES * KH];
__device__ int    g_deg[N_NODES];
__device__ int    g_off[N_NODES + 1];
__device__ int    g_cursor[N_NODES];
__device__ int    g_bsum[128];
__device__ int    g_psrc[E_EDGES];

// ---------------- P0: zero deg ----------------
__global__ void init_kernel() {
    int tid = blockIdx.x * blockDim.x + threadIdx.x;
    if (tid < N_NODES) g_deg[tid] = 0;
    if (tid < 128) g_bsum[tid] = 0;
}

// ---------------- P1: GEMM feat @ W (row-pair FFMA2) + fused el/er --------
#define BM 64
#define BK 32
__global__ __launch_bounds__(256) void gemm_kernel(const float* __restrict__ feat,
                                                   const float* __restrict__ W,
                                                   const float* __restrict__ attn_l,
                                                   const float* __restrict__ attn_r) {
    __shared__ __align__(16) float sXT[BK][BM + 4];
    __shared__ __align__(16) float sW[BK][F];
    const int row0 = blockIdx.x * BM;
    const int t  = threadIdx.x;
    const int tx = t & 31;
    const int ty = t >> 5;
    const int head = tx >> 2;
    const int sub  = tx & 3;

    float4 al = *(const float4*)&attn_l[head * DH + sub * 4];
    float4 ar = *(const float4*)&attn_r[head * DH + sub * 4];

    unsigned long long acc2[4][4];
#pragma unroll
    for (int p = 0; p < 4; p++)
#pragma unroll
        for (int c = 0; c < 4; c++) acc2[p][c] = 0ULL;

    for (int k0 = 0; k0 < IN_DIM; k0 += BK) {
#pragma unroll
        for (int i = 0; i < 2; i++) {
            int idx = t + i * 256;
            int r   = idx >> 3;
            int c4  = idx & 7;
            float4 v = make_float4(0.f, 0.f, 0.f, 0.f);
            int gr = row0 + r;
            if (gr < N_NODES) v = *(const float4*)&feat[gr * IN_DIM + k0 + c4 * 4];
            sXT[c4 * 4 + 0][r] = v.x;
            sXT[c4 * 4 + 1][r] = v.y;
            sXT[c4 * 4 + 2][r] = v.z;
            sXT[c4 * 4 + 3][r] = v.w;
        }
#pragma unroll
        for (int i = 0; i < 4; i++) {
            int idx = t + i * 256;
            int r   = idx >> 5;
            int c4  = idx & 31;
            *(float4*)&sW[r][c4 * 4] = *(const float4*)&W[(k0 + r) * F + c4 * 4];
        }
        __syncthreads();
#pragma unroll
        for (int kk = 0; kk < BK; kk++) {
            float4 wv = *(const float4*)&sW[kk][tx * 4];
            float4 xa = *(const float4*)&sXT[kk][ty * 8];
            float4 xb = *(const float4*)&sXT[kk][ty * 8 + 4];
            unsigned long long xp[4], wd[4];
            asm("mov.b64 %0, {%1, %2};" : "=l"(xp[0]) : "f"(xa.x), "f"(xa.y));
            asm("mov.b64 %0, {%1, %2};" : "=l"(xp[1]) : "f"(xa.z), "f"(xa.w));
            asm("mov.b64 %0, {%1, %2};" : "=l"(xp[2]) : "f"(xb.x), "f"(xb.y));
            asm("mov.b64 %0, {%1, %2};" : "=l"(xp[3]) : "f"(xb.z), "f"(xb.w));
            asm("mov.b64 %0, {%1, %1};" : "=l"(wd[0]) : "f"(wv.x));
            asm("mov.b64 %0, {%1, %1};" : "=l"(wd[1]) : "f"(wv.y));
            asm("mov.b64 %0, {%1, %1};" : "=l"(wd[2]) : "f"(wv.z));
            asm("mov.b64 %0, {%1, %1};" : "=l"(wd[3]) : "f"(wv.w));
#pragma unroll
            for (int p = 0; p < 4; p++)
#pragma unroll
                for (int c = 0; c < 4; c++)
                    asm("fma.rn.f32x2 %0, %1, %2, %3;"
                        : "=l"(acc2[p][c]) : "l"(xp[p]), "l"(wd[c]), "l"(acc2[p][c]));
        }
        __syncthreads();
    }

    float accf[8][4];
#pragma unroll
    for (int p = 0; p < 4; p++)
#pragma unroll
        for (int c = 0; c < 4; c++)
            asm("mov.b64 {%0, %1}, %2;"
                : "=f"(accf[2 * p][c]), "=f"(accf[2 * p + 1][c]) : "l"(acc2[p][c]));

#pragma unroll
    for (int r = 0; r < 8; r++) {
        int gr = row0 + ty * 8 + r;
        float a0 = accf[r][0], a1 = accf[r][1], a2 = accf[r][2], a3 = accf[r][3];
        float pl = a0 * al.x + a1 * al.y + a2 * al.z + a3 * al.w;
        float pr = a0 * ar.x + a1 * ar.y + a2 * ar.z + a3 * ar.w;
        pl += __shfl_xor_sync(0xffffffffu, pl, 1);
        pl += __shfl_xor_sync(0xffffffffu, pl, 2);
        pr += __shfl_xor_sync(0xffffffffu, pr, 1);
        pr += __shfl_xor_sync(0xffffffffu, pr, 2);
        if (gr < N_NODES) {
            __half2* hp = (__half2*)&g_feat_h[gr * F + tx * 4];
            hp[0] = __floats2half2_rn(a0, a1);
            hp[1] = __floats2half2_rn(a2, a3);
            if (sub == 0) {
                g_el[gr * KH + head] = pl;
                g_er[gr * KH + head] = pr;
            }
        }
    }
}

// ---------------- CSR build ----------------
__global__ void hist_kernel(const int* __restrict__ dst) {
    int e = blockIdx.x * blockDim.x + threadIdx.x;
    if (e < E_EDGES) atomicAdd(&g_deg[dst[e]], 1);
}

__global__ __launch_bounds__(SCAN_B) void scanA_kernel() {
    __shared__ int sm[SCAN_B];
    int tid = threadIdx.x;
    int gid = blockIdx.x * SCAN_B + tid;
    int v = (gid < N_NODES) ? g_deg[gid] : 0;
    sm[tid] = v;
    __syncthreads();
#pragma unroll
    for (int d = 1; d < SCAN_B; d <<= 1) {
        int t = (tid >= d) ? sm[tid - d] : 0;
        __syncthreads();
        sm[tid] += t;
        __syncthreads();
    }
    if (gid < N_NODES) g_off[gid] = sm[tid] - v;
    if (tid == SCAN_B - 1) g_bsum[blockIdx.x] = sm[tid];
}

__global__ __launch_bounds__(128) void scanB_kernel() {
    __shared__ int sm[128];
    int tid = threadIdx.x;
    int v = (tid < NBLK) ? g_bsum[tid] : 0;
    sm[tid] = v;
    __syncthreads();
#pragma unroll
    for (int d = 1; d < 128; d <<= 1) {
        int t = (tid >= d) ? sm[tid - d] : 0;
        __syncthreads();
        sm[tid] += t;
        __syncthreads();
    }
    g_bsum[tid] = sm[tid] - v;
}

__global__ void scanC_kernel() {
    int gid = blockIdx.x * blockDim.x + threadIdx.x;
    if (gid < N_NODES) {
        int off = g_off[gid] + g_bsum[gid >> 10];
        g_off[gid] = off;
        g_cursor[gid] = off;
    }
    if (gid == 0) g_off[N_NODES] = E_EDGES;
}

__global__ void scatter_kernel(const int* __restrict__ src,
                               const int* __restrict__ dst) {
    int e = blockIdx.x * blockDim.x + threadIdx.x;
    if (e >= E_EDGES) return;
    int pos = atomicAdd(&g_cursor[dst[e]], 1);
    g_psrc[pos] = src[e];
}

// ---------------- P3: single-pass warp-per-dst gather ----------------
// out = (sum_i ex_i * f_i) / (sum_i ex_i)  -- no denominator prepass needed.
__device__ __forceinline__ void edge_step(int s, float er_k, int khead, int lane,
                                          float4& acc, float& ssum) {
    float v = __ldg(&g_el[s * KH + khead]) + er_k;
    v = (v > 0.f) ? v : NEG_SLOPE * v;
    float ex = __expf(v);
    ssum += ex;
    unsigned long long pk = *(const unsigned long long*)&g_feat_h[s * F + lane * 4];
    __half2 h0 = ((const __half2*)&pk)[0];
    __half2 h1 = ((const __half2*)&pk)[1];
    float2 f0 = __half22float2(h0);
    float2 f1 = __half22float2(h1);
    acc.x = fmaf(ex, f0.x, acc.x);
    acc.y = fmaf(ex, f0.y, acc.y);
    acc.z = fmaf(ex, f1.x, acc.z);
    acc.w = fmaf(ex, f1.y, acc.w);
}

__global__ __launch_bounds__(256) void agg_csr_kernel(float* __restrict__ out) {
    __shared__ int s_src[8][CAP];
    int wid  = threadIdx.x >> 5;
    int lane = threadIdx.x & 31;
    int w = blockIdx.x * 8 + wid;
    if (w >= N_NODES) return;
    int off0 = g_off[w];
    int off1 = g_off[w + 1];
    int deg  = off1 - off0;
    int cached = (deg < CAP) ? deg : CAP;

    for (int i = lane; i < cached; i += 32) s_src[wid][i] = g_psrc[off0 + i];

    int khead = lane >> 2;
    float er_k = __ldg(&g_er[w * KH + khead]);
    __syncwarp();

    float4 acc = make_float4(0.f, 0.f, 0.f, 0.f);
    float ssum = 0.f;
    int i = 0;
    for (; i + 3 < cached; i += 4) {
        int s0 = s_src[wid][i],     s1 = s_src[wid][i + 1];
        int s2 = s_src[wid][i + 2], s3 = s_src[wid][i + 3];
        edge_step(s0, er_k, khead, lane, acc, ssum);
        edge_step(s1, er_k, khead, lane, acc, ssum);
        edge_step(s2, er_k, khead, lane, acc, ssum);
        edge_step(s3, er_k, khead, lane, acc, ssum);
    }
    for (; i < cached; i++) edge_step(s_src[wid][i], er_k, khead, lane, acc, ssum);
    for (; i < deg; i++)    edge_step(g_psrc[off0 + i], er_k, khead, lane, acc, ssum);

    float inv = (deg > 0) ? __fdividef(1.f, ssum) : 0.f;
    *(float4*)&out[w * F + lane * 4] =
        make_float4(acc.x * inv, acc.y * inv, acc.z * inv, acc.w * inv);
}

// ---------------- launch (CSR chain overlapped with GEMM) ----------------
extern "C" void kernel_launch(void* const* d_in, const int* in_sizes, int n_in,
                              void* d_out, int out_size) {
    const float* feat   = (const float*)d_in[0];
    const float* W      = (const float*)d_in[1];
    const float* attn_l = (const float*)d_in[2];
    const float* attn_r = (const float*)d_in[3];
    const int*   src    = (const int*)d_in[4];
    const int*   dst    = (const int*)d_in[5];
    float* out = (float*)d_out;

    static cudaStream_t s2 = nullptr;
    static cudaEvent_t evFork = nullptr, evCsr = nullptr;
    if (s2 == nullptr) {
        cudaStreamCreateWithFlags(&s2, cudaStreamNonBlocking);
        cudaEventCreateWithFlags(&evFork, cudaEventDisableTiming);
        cudaEventCreateWithFlags(&evCsr, cudaEventDisableTiming);
    }

    const int T = 256;
    cudaEventRecord(evFork, 0);
    cudaStreamWaitEvent(s2, evFork, 0);
    init_kernel<<<(N_NODES + T - 1) / T, T, 0, s2>>>();
    hist_kernel<<<(E_EDGES + T - 1) / T, T, 0, s2>>>(dst);
    scanA_kernel<<<NBLK, SCAN_B, 0, s2>>>();
    scanB_kernel<<<1, 128, 0, s2>>>();
    scanC_kernel<<<(N_NODES + T - 1) / T, T, 0, s2>>>();
    scatter_kernel<<<(E_EDGES + T - 1) / T, T, 0, s2>>>(src, dst);
    cudaEventRecord(evCsr, s2);

    gemm_kernel<<<(N_NODES + BM - 1) / BM, T>>>(feat, W, attn_l, attn_r);

    cudaStreamWaitEvent(0, evCsr, 0);
    agg_csr_kernel<<<(N_NODES + 7) / 8, T>>>(out);
}

// round 8
// speedup vs baseline: 2.8213x; 1.0516x over previous
#include <cuda_runtime.h>
#include <cuda_fp16.h>

#define N_NODES 100000
#define E_EDGES 1600000
#define IN_DIM  128
#define KH      8
#define DH      16
#define F       128
#define NEG_SLOPE 0.2f
#define SCAN_B  1024
#define NBLK    ((N_NODES + SCAN_B - 1) / SCAN_B)   // 98
#define CAP     128

// ---------------- scratch ----------------
__device__ __half g_feat_h[N_NODES * F];
__device__ float  g_el[N_NODES * KH];
__device__ float  g_er[N_NODES * KH];
__device__ int    g_deg[N_NODES];
__device__ int    g_off[N_NODES + 1];
__device__ int    g_cursor[N_NODES];
__device__ int    g_psrc[E_EDGES];
__device__ unsigned long long g_desc[NBLK];   // hi32: status (0/1/2), lo32: value

// ---------------- P0: zero deg + scan descriptors ----------------
__global__ void init_kernel() {
    int tid = blockIdx.x * blockDim.x + threadIdx.x;
    if (tid < N_NODES) g_deg[tid] = 0;
    if (tid < NBLK) g_desc[tid] = 0ULL;
}

// ---------------- P1: GEMM feat @ W (row-pair FFMA2, reg-pipelined) -------
#define BM 64
#define BK 32
__global__ __launch_bounds__(256) void gemm_kernel(const float* __restrict__ feat,
                                                   const float* __restrict__ W,
                                                   const float* __restrict__ attn_l,
                                                   const float* __restrict__ attn_r) {
    __shared__ __align__(16) float sXT[BK][BM + 4];
    __shared__ __align__(16) float sW[BK][F];
    const int row0 = blockIdx.x * BM;
    const int t  = threadIdx.x;
    const int tx = t & 31;
    const int ty = t >> 5;
    const int head = tx >> 2;
    const int sub  = tx & 3;

    float4 al = *(const float4*)&attn_l[head * DH + sub * 4];
    float4 ar = *(const float4*)&attn_r[head * DH + sub * 4];

    // load-index precompute
    const int xr_  = (t) >> 3,        xc_  = (t) & 7;         // tile-x part 0
    const int xr2_ = (t + 256) >> 3,  xc2_ = (t + 256) & 7;   // tile-x part 1
    int gxr  = row0 + xr_;  if (gxr  >= N_NODES) gxr  = N_NODES - 1;
    int gxr2 = row0 + xr2_; if (gxr2 >= N_NODES) gxr2 = N_NODES - 1;

    float4 xv0, xv1, wv0, wv1, wv2, wv3;
    // prologue: tile 0 loads
    xv0 = *(const float4*)&feat[gxr  * IN_DIM + 0 + xc_  * 4];
    xv1 = *(const float4*)&feat[gxr2 * IN_DIM + 0 + xc2_ * 4];
    {
        int r0_ = t >> 5, c0_ = t & 31;
        wv0 = *(const float4*)&W[(0 + r0_ +  0) * F + c0_ * 4];
        wv1 = *(const float4*)&W[(0 + r0_ +  8) * F + c0_ * 4];
        wv2 = *(const float4*)&W[(0 + r0_ + 16) * F + c0_ * 4];
        wv3 = *(const float4*)&W[(0 + r0_ + 24) * F + c0_ * 4];
    }

    unsigned long long acc2[4][4];
#pragma unroll
    for (int p = 0; p < 4; p++)
#pragma unroll
        for (int c = 0; c < 4; c++) acc2[p][c] = 0ULL;

#pragma unroll
    for (int it = 0; it < IN_DIM / BK; it++) {
        // store regs -> smem
        sXT[xc_  * 4 + 0][xr_]  = xv0.x;
        sXT[xc_  * 4 + 1][xr_]  = xv0.y;
        sXT[xc_  * 4 + 2][xr_]  = xv0.z;
        sXT[xc_  * 4 + 3][xr_]  = xv0.w;
        sXT[xc2_ * 4 + 0][xr2_] = xv1.x;
        sXT[xc2_ * 4 + 1][xr2_] = xv1.y;
        sXT[xc2_ * 4 + 2][xr2_] = xv1.z;
        sXT[xc2_ * 4 + 3][xr2_] = xv1.w;
        {
            int r0_ = t >> 5, c0_ = t & 31;
            *(float4*)&sW[r0_ +  0][c0_ * 4] = wv0;
            *(float4*)&sW[r0_ +  8][c0_ * 4] = wv1;
            *(float4*)&sW[r0_ + 16][c0_ * 4] = wv2;
            *(float4*)&sW[r0_ + 24][c0_ * 4] = wv3;
        }
        __syncthreads();

        // prefetch next tile into regs (overlaps compute below)
        if (it + 1 < IN_DIM / BK) {
            int k0n = (it + 1) * BK;
            xv0 = *(const float4*)&feat[gxr  * IN_DIM + k0n + xc_  * 4];
            xv1 = *(const float4*)&feat[gxr2 * IN_DIM + k0n + xc2_ * 4];
            int r0_ = t >> 5, c0_ = t & 31;
            wv0 = *(const float4*)&W[(k0n + r0_ +  0) * F + c0_ * 4];
            wv1 = *(const float4*)&W[(k0n + r0_ +  8) * F + c0_ * 4];
            wv2 = *(const float4*)&W[(k0n + r0_ + 16) * F + c0_ * 4];
            wv3 = *(const float4*)&W[(k0n + r0_ + 24) * F + c0_ * 4];
        }

#pragma unroll
        for (int kk = 0; kk < BK; kk++) {
            float4 wv = *(const float4*)&sW[kk][tx * 4];
            float4 xa = *(const float4*)&sXT[kk][ty * 8];
            float4 xb = *(const float4*)&sXT[kk][ty * 8 + 4];
            unsigned long long xp[4], wd[4];
            asm("mov.b64 %0, {%1, %2};" : "=l"(xp[0]) : "f"(xa.x), "f"(xa.y));
            asm("mov.b64 %0, {%1, %2};" : "=l"(xp[1]) : "f"(xa.z), "f"(xa.w));
            asm("mov.b64 %0, {%1, %2};" : "=l"(xp[2]) : "f"(xb.x), "f"(xb.y));
            asm("mov.b64 %0, {%1, %2};" : "=l"(xp[3]) : "f"(xb.z), "f"(xb.w));
            asm("mov.b64 %0, {%1, %1};" : "=l"(wd[0]) : "f"(wv.x));
            asm("mov.b64 %0, {%1, %1};" : "=l"(wd[1]) : "f"(wv.y));
            asm("mov.b64 %0, {%1, %1};" : "=l"(wd[2]) : "f"(wv.z));
            asm("mov.b64 %0, {%1, %1};" : "=l"(wd[3]) : "f"(wv.w));
#pragma unroll
            for (int p = 0; p < 4; p++)
#pragma unroll
                for (int c = 0; c < 4; c++)
                    asm("fma.rn.f32x2 %0, %1, %2, %3;"
                        : "=l"(acc2[p][c]) : "l"(xp[p]), "l"(wd[c]), "l"(acc2[p][c]));
        }
        __syncthreads();
    }

    float accf[8][4];
#pragma unroll
    for (int p = 0; p < 4; p++)
#pragma unroll
        for (int c = 0; c < 4; c++)
            asm("mov.b64 {%0, %1}, %2;"
                : "=f"(accf[2 * p][c]), "=f"(accf[2 * p + 1][c]) : "l"(acc2[p][c]));

#pragma unroll
    for (int r = 0; r < 8; r++) {
        int gr = row0 + ty * 8 + r;
        float a0 = accf[r][0], a1 = accf[r][1], a2 = accf[r][2], a3 = accf[r][3];
        float pl = a0 * al.x + a1 * al.y + a2 * al.z + a3 * al.w;
        float pr = a0 * ar.x + a1 * ar.y + a2 * ar.z + a3 * ar.w;
        pl += __shfl_xor_sync(0xffffffffu, pl, 1);
        pl += __shfl_xor_sync(0xffffffffu, pl, 2);
        pr += __shfl_xor_sync(0xffffffffu, pr, 1);
        pr += __shfl_xor_sync(0xffffffffu, pr, 2);
        if (gr < N_NODES) {
            __half2* hp = (__half2*)&g_feat_h[gr * F + tx * 4];
            hp[0] = __floats2half2_rn(a0, a1);
            hp[1] = __floats2half2_rn(a2, a3);
            if (sub == 0) {
                g_el[gr * KH + head] = pl;
                g_er[gr * KH + head] = pr;
            }
        }
    }
}

// ---------------- CSR build ----------------
__global__ void hist_kernel(const int* __restrict__ dst) {
    int e = blockIdx.x * blockDim.x + threadIdx.x;
    if (e < E_EDGES) atomicAdd(&g_deg[dst[e]], 1);
}

__device__ __forceinline__ unsigned long long desc_ld(int idx) {
    unsigned long long v;
    asm volatile("ld.volatile.global.u64 %0, [%1];" : "=l"(v) : "l"(&g_desc[idx]));
    return v;
}
__device__ __forceinline__ void desc_st(int idx, unsigned long long v) {
    asm volatile("st.volatile.global.u64 [%0], %1;" :: "l"(&g_desc[idx]), "l"(v) : "memory");
}

// single-kernel decoupled-lookback exclusive scan of g_deg -> g_off/g_cursor
__global__ __launch_bounds__(SCAN_B) void scan_kernel() {
    __shared__ int warp_sums[32];
    __shared__ int s_bprefix;
    int tid  = threadIdx.x;
    int lane = tid & 31;
    int wid  = tid >> 5;
    int b    = blockIdx.x;
    int gid  = b * SCAN_B + tid;
    int v = (gid < N_NODES) ? g_deg[gid] : 0;

    // warp inclusive scan
    int x = v;
#pragma unroll
    for (int d = 1; d < 32; d <<= 1) {
        int tv = __shfl_up_sync(0xffffffffu, x, d);
        if (lane >= d) x += tv;
    }
    if (lane == 31) warp_sums[wid] = x;
    __syncthreads();
    if (wid == 0) {
        int y = warp_sums[lane];
#pragma unroll
        for (int d = 1; d < 32; d <<= 1) {
            int tv = __shfl_up_sync(0xffffffffu, y, d);
            if (lane >= d) y += tv;
        }
        warp_sums[lane] = y;
    }
    __syncthreads();
    int block_total = warp_sums[31];
    int excl = ((wid > 0) ? warp_sums[wid - 1] : 0) + x - v;

    if (wid == 0) {
        if (b == 0) {
            if (lane == 0) {
                desc_st(0, (2ULL << 32) | (unsigned)block_total);
                s_bprefix = 0;
            }
        } else {
            if (lane == 0) desc_st(b, (1ULL << 32) | (unsigned)block_total);
            int prefix = 0;
            int look = b - 1;
            while (look >= 0) {
                int idx = look - lane;
                unsigned long long d = 0;
                if (idx >= 0) {
                    do { d = desc_ld(idx); } while ((d >> 32) == 0ULL);
                }
                unsigned st = (idx >= 0) ? (unsigned)(d >> 32) : 0u;
                unsigned mask2 = __ballot_sync(0xffffffffu, st == 2u);
                int stop = mask2 ? (__ffs(mask2) - 1) : 32;
                int contrib = (idx >= 0 && lane <= stop) ? (int)(d & 0xffffffffULL) : 0;
#pragma unroll
                for (int dd = 16; dd > 0; dd >>= 1)
                    contrib += __shfl_xor_sync(0xffffffffu, contrib, dd);
                prefix += contrib;
                if (mask2) break;
                look -= 32;
            }
            if (lane == 0) {
                desc_st(b, (2ULL << 32) | (unsigned)(prefix + block_total));
                s_bprefix = prefix;
            }
        }
    }
    __syncthreads();
    int off = s_bprefix + excl;
    if (gid < N_NODES) { g_off[gid] = off; g_cursor[gid] = off; }
    if (b == 0 && tid == 0) g_off[N_NODES] = E_EDGES;
}

__global__ void scatter_kernel(const int* __restrict__ src,
                               const int* __restrict__ dst) {
    int e = blockIdx.x * blockDim.x + threadIdx.x;
    if (e >= E_EDGES) return;
    int pos = atomicAdd(&g_cursor[dst[e]], 1);
    g_psrc[pos] = src[e];
}

// ---------------- P3: single-pass warp-per-dst gather ----------------
__device__ __forceinline__ void edge_math(float elv, float er_k,
                                          unsigned long long pk,
                                          float4& acc, float& ssum) {
    float v = elv + er_k;
    v = (v > 0.f) ? v : NEG_SLOPE * v;
    float ex = __expf(v);
    ssum += ex;
    __half2 h0 = ((const __half2*)&pk)[0];
    __half2 h1 = ((const __half2*)&pk)[1];
    float2 f0 = __half22float2(h0);
    float2 f1 = __half22float2(h1);
    acc.x = fmaf(ex, f0.x, acc.x);
    acc.y = fmaf(ex, f0.y, acc.y);
    acc.z = fmaf(ex, f1.x, acc.z);
    acc.w = fmaf(ex, f1.y, acc.w);
}

__global__ __launch_bounds__(256) void agg_csr_kernel(float* __restrict__ out) {
    __shared__ int s_src[8][CAP];
    int wid  = threadIdx.x >> 5;
    int lane = threadIdx.x & 31;
    int w = blockIdx.x * 8 + wid;
    if (w >= N_NODES) return;
    int off0 = g_off[w];
    int off1 = g_off[w + 1];
    int deg  = off1 - off0;
    int cached = (deg < CAP) ? deg : CAP;

    for (int i = lane; i < cached; i += 32) s_src[wid][i] = g_psrc[off0 + i];

    int khead = lane >> 2;
    float er_k = __ldg(&g_er[w * KH + khead]);
    __syncwarp();

    float4 acc = make_float4(0.f, 0.f, 0.f, 0.f);
    float ssum = 0.f;
    int i = 0;
    for (; i + 7 < cached; i += 8) {
        int s[8];
#pragma unroll
        for (int j = 0; j < 8; j++) s[j] = s_src[wid][i + j];
        float elv[8];
        unsigned long long pk[8];
#pragma unroll
        for (int j = 0; j < 8; j++) elv[j] = __ldg(&g_el[s[j] * KH + khead]);
#pragma unroll
        for (int j = 0; j < 8; j++)
            pk[j] = *(const unsigned long long*)&g_feat_h[s[j] * F + lane * 4];
#pragma unroll
        for (int j = 0; j < 8; j++) edge_math(elv[j], er_k, pk[j], acc, ssum);
    }
    for (; i < cached; i++) {
        int s = s_src[wid][i];
        float elv = __ldg(&g_el[s * KH + khead]);
        unsigned long long pk = *(const unsigned long long*)&g_feat_h[s * F + lane * 4];
        edge_math(elv, er_k, pk, acc, ssum);
    }
    for (; i < deg; i++) {
        int s = g_psrc[off0 + i];
        float elv = __ldg(&g_el[s * KH + khead]);
        unsigned long long pk = *(const unsigned long long*)&g_feat_h[s * F + lane * 4];
        edge_math(elv, er_k, pk, acc, ssum);
    }

    float inv = (deg > 0) ? __fdividef(1.f, ssum) : 0.f;
    *(float4*)&out[w * F + lane * 4] =
        make_float4(acc.x * inv, acc.y * inv, acc.z * inv, acc.w * inv);
}

// ---------------- launch (CSR chain overlapped with GEMM) ----------------
extern "C" void kernel_launch(void* const* d_in, const int* in_sizes, int n_in,
                              void* d_out, int out_size) {
    const float* feat   = (const float*)d_in[0];
    const float* W      = (const float*)d_in[1];
    const float* attn_l = (const float*)d_in[2];
    const float* attn_r = (const float*)d_in[3];
    const int*   src    = (const int*)d_in[4];
    const int*   dst    = (const int*)d_in[5];
    float* out = (float*)d_out;

    static cudaStream_t s2 = nullptr;
    static cudaEvent_t evFork = nullptr, evCsr = nullptr;
    if (s2 == nullptr) {
        cudaStreamCreateWithFlags(&s2, cudaStreamNonBlocking);
        cudaEventCreateWithFlags(&evFork, cudaEventDisableTiming);
        cudaEventCreateWithFlags(&evCsr, cudaEventDisableTiming);
    }

    const int T = 256;
    cudaEventRecord(evFork, 0);
    cudaStreamWaitEvent(s2, evFork, 0);
    // launches 0..3 on s2 (CSR chain)
    init_kernel<<<(N_NODES + T - 1) / T, T, 0, s2>>>();
    hist_kernel<<<(E_EDGES + T - 1) / T, T, 0, s2>>>(dst);
    scan_kernel<<<NBLK, SCAN_B, 0, s2>>>();
    scatter_kernel<<<(E_EDGES + T - 1) / T, T, 0, s2>>>(src, dst);
    cudaEventRecord(evCsr, s2);

    // launch 4: GEMM on origin stream (concurrent with CSR)
    gemm_kernel<<<(N_NODES + BM - 1) / BM, T>>>(feat, W, attn_l, attn_r);

    // launch 5: aggregate (ncu -s 5 captures this)
    cudaStreamWaitEvent(0, evCsr, 0);
    agg_csr_kernel<<<(N_NODES + 7) / 8, T>>>(out);
}